// round 16
// baseline (speedup 1.0000x reference)
#include <cuda_runtime.h>
#include <math.h>

#define BB 64
#define TT 128
#define DD 512
#define NBD (BB*DD)
#define BTD (BB*TT*DD)
#define G_CTAS 128
#define AT_OFF   15360
#define BS_OFF   23552
#define BP0_OFF  32768
#define BP1_OFF  41984
#define SRED_OFF 51200
#define SCAN_SMEM 222208   /* 55552 floats */

typedef unsigned long long u64;

__device__ float g_Qt[TT*NBD];     // [t][k][b]
__device__ float g_Kt[TT*NBD];     // [t][k][b]
__device__ float g_K [TT*NBD];     // [t][b][k]
__device__ float g_V [TT*NBD];     // [t][b][k]
__device__ float g_th[TT], g_et[TT], g_al[TT];
__device__ float g_W1[DD*DD], g_M1w[DD*DD], g_b1[DD], g_M1b[DD];
__device__ float g_W2p[2][DD*DD];
__device__ float g_M2w[DD*DD], g_b2[DD], g_M2b[DD];
__device__ float g_W1t[DD*DD], g_W2t[DD*DD];   // [k][n]
__device__ float g_h[2*NBD];
__device__ float g_ht[2*NBD];      // [n][m] relu-applied
__device__ float g_diff[NBD];
__device__ float g_difft[NBD];     // [n][b]
__device__ float g_dpre[NBD];
__device__ float g_loss[TT];
__device__ unsigned g_barcnt[32][32];
__device__ unsigned g_pcnt[2][8][32];

__device__ __forceinline__ u64 pk2(float x, float y){
    u64 r; asm("mov.b64 %0, {%1, %2};" : "=l"(r) : "f"(x), "f"(y)); return r;
}
__device__ __forceinline__ void fma2(u64 &c, u64 a, u64 b){
    asm("fma.rn.f32x2 %0, %1, %2, %0;" : "+l"(c) : "l"(a), "l"(b));
}
__device__ __forceinline__ u64 add2(u64 a, u64 b){
    u64 r; asm("add.rn.f32x2 %0, %1, %2;" : "=l"(r) : "l"(a), "l"(b)); return r;
}
__device__ __forceinline__ float2 up2(u64 v){
    float lo, hi; asm("mov.b64 {%0, %1}, %2;" : "=f"(lo), "=f"(hi) : "l"(v));
    return make_float2(lo, hi);
}
__device__ __forceinline__ unsigned smaddr(const void* p){
    return (unsigned)__cvta_generic_to_shared(p);
}
__device__ __forceinline__ void cpa(float* d, const float* s){
    asm volatile("cp.async.cg.shared.global [%0], [%1], 16;" :: "r"(smaddr(d)), "l"(s));
}
#define COMMIT asm volatile("cp.async.commit_group;")
#define WAITG(n) asm volatile("cp.async.wait_group %0;" :: "n"(n))

// prefetch chunks 0,1 of B (rows 0..255, k-major stride DD) into dst; 1 group
__device__ __forceinline__ void preB2(float* dst, const float* Bk, int tid){
    #pragma unroll
    for (int i = 0; i < 4; i++){
        int e = tid + i*512; int row = e >> 3, nq = e & 7;
        cpa(dst + (row >> 7)*4608 + (row & 127)*36 + nq*4, &Bk[(size_t)row*DD + nq*4]);
    }
    COMMIT;
}
// prefetch full A (k-major [512][Ms], rows moff..+16) into At; 1 group
__device__ __forceinline__ void preA(float* At, const float* Akt, int Ms, int moff, int tid){
    #pragma unroll
    for (int i = 0; i < 4; i++){
        int e = tid + i*512; int k = e >> 2, mq4 = (e & 3)*4;
        cpa(&At[k*16 + mq4], &Akt[(size_t)k*Ms + moff + mq4]);
    }
    COMMIT;
}

__device__ __forceinline__ void gbar(unsigned &gen){
    __syncthreads();
    if (threadIdx.x < 32){
        if (threadIdx.x == 0){
            unsigned d;
            asm volatile("atom.acq_rel.gpu.global.add.u32 %0, [%1], 1;"
                         : "=r"(d) : "l"(&g_barcnt[blockIdx.x & 31][0]) : "memory");
        }
        unsigned target = (gen + 1u) * 4u, v;
        do {
            asm volatile("ld.acquire.gpu.global.u32 %0, [%1];"
                         : "=r"(v) : "l"(&g_barcnt[threadIdx.x][0]) : "memory");
        } while (__any_sync(0xffffffffu, v < target));
    }
    __syncthreads();
    gen++;
}
__device__ __forceinline__ void gbar_p(int type, unsigned &pgen, bool producer){
    __syncthreads();
    if (threadIdx.x < 8){
        if (threadIdx.x == 0 && producer){
            unsigned d;
            asm volatile("atom.acq_rel.gpu.global.add.u32 %0, [%1], 1;"
                         : "=r"(d) : "l"(&g_pcnt[type][blockIdx.x & 7][0]) : "memory");
        }
        unsigned target = (pgen + 1u) * 8u, v;
        do {
            asm volatile("ld.acquire.gpu.global.u32 %0, [%1];"
                         : "=r"(v) : "l"(&g_pcnt[type][threadIdx.x][0]) : "memory");
        } while (__any_sync(0xffu, v < target));
    }
    __syncthreads();
    pgen++;
}

__global__ void k_init(const float* __restrict__ W1, const float* __restrict__ b1,
                       const float* __restrict__ W2, const float* __restrict__ b2) {
    int i = blockIdx.x * 256 + threadIdx.x;
    if (i < DD*DD) {
        g_W1[i] = W1[i]; g_M1w[i] = 0.f; g_W2p[0][i] = W2[i]; g_M2w[i] = 0.f;
        int tr = (i & 511) * 512 + (i >> 9);
        g_W1t[tr] = W1[i]; g_W2t[tr] = W2[i];
    }
    if (i < DD) { g_b1[i] = b1[i]; g_M1b[i] = 0.f; g_b2[i] = b2[i]; g_M2b[i] = 0.f; }
    if (i < TT) g_loss[i] = 0.f;
    if (i < 1024) ((unsigned*)g_barcnt)[i] = 0u;
    if (i < 512) ((unsigned*)g_pcnt)[i] = 0u;
}

__global__ void k_gates(const float* __restrict__ x,
                        const float* __restrict__ thw, const float* __restrict__ thb,
                        const float* __restrict__ etw, const float* __restrict__ etb,
                        const float* __restrict__ alw, const float* __restrict__ alb) {
    int t = blockIdx.x, tid = threadIdx.x, lane = tid & 31, warp = tid >> 5;
    __shared__ float red[8];
    for (int g = 0; g < 3; g++) {
        const float* w = (g == 0) ? thw : ((g == 1) ? etw : alw);
        float b0 = (g == 0) ? thb[0] : ((g == 1) ? etb[0] : alb[0]);
        float acc = 0.f;
        for (int bi = warp; bi < BB; bi += 8) {
            const float* xr = x + ((size_t)bi * TT + t) * DD;
            float s = 0.f;
            for (int k = lane; k < DD; k += 32) s += xr[k] * w[k];
            #pragma unroll
            for (int o = 16; o; o >>= 1) s += __shfl_down_sync(0xffffffffu, s, o);
            if (lane == 0) acc += 1.f / (1.f + expf(-(s + b0)));
        }
        if (lane == 0) red[warp] = acc;
        __syncthreads();
        if (tid == 0) {
            float s = 0.f;
            #pragma unroll
            for (int i = 0; i < 8; i++) s += red[i];
            s *= (1.f / (float)BB);
            if (g == 0) g_th[t] = s; else if (g == 1) g_et[t] = s; else g_al[t] = s;
        }
        __syncthreads();
    }
}

__global__ __launch_bounds__(256) void k_qkv(const float* __restrict__ x,
                       const float* __restrict__ WQ, const float* __restrict__ WK,
                       const float* __restrict__ WV) {
    __shared__ __align__(16) float qsm[4352];
    float (*As2)[68] = (float(*)[68])qsm;
    float (*Bsk)[68] = (float(*)[68])(qsm + 2176);
    int n0 = blockIdx.x * 64, m0 = blockIdx.y * 64, z = blockIdx.z;
    const float* W = (z == 0) ? WQ : ((z == 1) ? WK : WV);
    int tid = threadIdx.x;
    int r0 = (tid >> 4) * 4, c0 = (tid & 15) * 4;
    u64 acc[4][2];
    #pragma unroll
    for (int i = 0; i < 4; i++) { acc[i][0] = 0ull; acc[i][1] = 0ull; }
    for (int kb = 0; kb < 16; kb++) {
        #pragma unroll
        for (int i = 0; i < 2; i++) {
            int e = tid + i*256; int row = e >> 3, kq = e & 7;
            int m = m0 + row;
            float4 xv = *(const float4*)&x[((size_t)(m & 63)*TT + (m >> 6))*DD + kb*32 + kq*4];
            As2[4*kq+0][row]=xv.x; As2[4*kq+1][row]=xv.y; As2[4*kq+2][row]=xv.z; As2[4*kq+3][row]=xv.w;
            float4 wv = *(const float4*)&W[(size_t)(n0 + row)*DD + kb*32 + kq*4];
            Bsk[4*kq+0][row]=wv.x; Bsk[4*kq+1][row]=wv.y; Bsk[4*kq+2][row]=wv.z; Bsk[4*kq+3][row]=wv.w;
        }
        __syncthreads();
        #pragma unroll 8
        for (int kk = 0; kk < 32; kk++) {
            float4 a4 = *(const float4*)&As2[kk][r0];
            ulonglong2 bb = *(const ulonglong2*)&Bsk[kk][c0];
            u64 sx;
            sx = pk2(a4.x,a4.x); fma2(acc[0][0],sx,bb.x); fma2(acc[0][1],sx,bb.y);
            sx = pk2(a4.y,a4.y); fma2(acc[1][0],sx,bb.x); fma2(acc[1][1],sx,bb.y);
            sx = pk2(a4.z,a4.z); fma2(acc[2][0],sx,bb.x); fma2(acc[2][1],sx,bb.y);
            sx = pk2(a4.w,a4.w); fma2(acc[3][0],sx,bb.x); fma2(acc[3][1],sx,bb.y);
        }
        __syncthreads();
    }
    float (*T)[68] = (float(*)[68])qsm;
    #pragma unroll
    for (int i = 0; i < 4; i++) {
        float2 p0 = up2(acc[i][0]), p1 = up2(acc[i][1]);
        float4 v = make_float4(p0.x, p0.y, p1.x, p1.y);
        if (z == 2) { *(float4*)&g_V[(size_t)(m0+r0+i)*DD + n0 + c0] = v; }
        else {
            if (z == 1) *(float4*)&g_K[(size_t)(m0+r0+i)*DD + n0 + c0] = v;
            T[c0+0][r0+i] = p0.x; T[c0+1][r0+i] = p0.y;
            T[c0+2][r0+i] = p1.x; T[c0+3][r0+i] = p1.y;
        }
    }
    if (z < 2) {
        __syncthreads();
        float* Ot = ((z == 0) ? g_Qt : g_Kt) + (size_t)(m0 >> 6)*NBD;
        #pragma unroll
        for (int i = 0; i < 4; i++) {
            int e = tid + i*256;
            int nl = e >> 4, b4 = (e & 15) * 4;
            *(float4*)&Ot[(size_t)(n0 + nl)*64 + b4] = *(float4*)&T[nl][b4];
        }
    }
}

// shared inner chunk: 16 k-steps over A(At, 16-wide rows) x B(36-stride rows)
__device__ __forceinline__ void chunk16(const float* ap, const float* bp,
                                        u64 &a0, u64 &a1, u64 &a2, u64 &a3){
    #pragma unroll
    for (int kk = 0; kk < 16; kk++) {
        float4 a = *(const float4*)(ap + kk*16);
        u64 b = *(const u64*)(bp + kk*36);
        fma2(a0, pk2(a.x,a.x), b);
        fma2(a1, pk2(a.y,a.y), b);
        fma2(a2, pk2(a.z,a.z), b);
        fma2(a3, pk2(a.w,a.w), b);
    }
}
__device__ __forceinline__ void sredw(float* sm, int tid, u64 a0, u64 a1, u64 a2, u64 a3){
    u64* sred = (u64*)(sm + SRED_OFF);
    int ks = tid >> 6, g = tid & 63, mq4 = (g >> 4) * 4, cv = g & 15;
    u64* rp = &sred[(ks*16 + mq4)*17 + cv];
    rp[0] = a0; rp[17] = a1; rp[34] = a2; rp[51] = a3;
    __syncthreads();
}
__device__ __forceinline__ float2 sredr(float* sm, int tid){
    u64* sred = (u64*)(sm + SRED_OFF);
    float2 T = make_float2(0.f, 0.f);
    if (tid < 256) {
        int m = tid >> 4, cvv = tid & 15;
        u64 acc = 0ull;
        #pragma unroll
        for (int k2 = 0; k2 < 8; k2++) acc = add2(acc, sred[(k2*16 + m)*17 + cvv]);
        T = up2(acc);
    }
    return T;
}

// H-variant: A pre-loaded in At (via PA group), B streamed 3-buffer (Bs0,Bs1,Bp0).
__device__ __forceinline__ float2 sgemmH(const float* __restrict__ Bk, float* sm, int tid){
    float* At = sm + AT_OFF;
    float* B0 = sm + BS_OFF, *B1 = sm + BS_OFF + 4608, *B2 = sm + BP0_OFF;
    float* bufs[4] = {B0, B1, B2, B0};
    #pragma unroll
    for (int c = 0; c < 3; c++){
        #pragma unroll
        for (int i = 0; i < 2; i++){
            int e = tid + i*512; int kq = e >> 3, nq = e & 7;
            cpa(bufs[c] + kq*36 + nq*4, &Bk[(size_t)(c*128 + kq)*DD + nq*4]);
        }
        COMMIT;
    }
    int ks = tid >> 6, g = tid & 63, mq4 = (g >> 4) * 4, cv = g & 15;
    u64 a0=0ull, a1=0ull, a2=0ull, a3=0ull;
    #pragma unroll
    for (int c = 0; c < 4; c++){
        if (c == 0) WAITG(2);
        else if (c == 3) WAITG(0);
        else WAITG(1);
        __syncthreads();
        if (c == 1){
            #pragma unroll
            for (int i = 0; i < 2; i++){
                int e = tid + i*512; int kq = e >> 3, nq = e & 7;
                cpa(B0 + kq*36 + nq*4, &Bk[(size_t)(384 + kq)*DD + nq*4]);
            }
            COMMIT;
        }
        chunk16(At + (c*128 + ks*16)*16 + mq4, bufs[c] + (ks*16)*36 + 2*cv, a0,a1,a2,a3);
    }
    sredw(sm, tid, a0,a1,a2,a3);
    return sredr(sm, tid);
}

// P-variant: B chunks 0,1 prefetched in Bpre; A + B chunks 2,3 streamed (G0,G1).
__device__ __forceinline__ float2 sgemmP(const float* __restrict__ Akt, int Ms, int moff,
                                         const float* __restrict__ Bk, float* Bpre,
                                         float* sm, int tid){
    float* At = sm + AT_OFF;
    float* B2 = sm + BS_OFF, *B3 = sm + BS_OFF + 4608;
    // G0: full A + B chunk2
    #pragma unroll
    for (int i = 0; i < 4; i++){
        int e = tid + i*512; int k = e >> 2, mq = (e & 3)*4;
        cpa(&At[k*16 + mq], &Akt[(size_t)k*Ms + moff + mq]);
    }
    #pragma unroll
    for (int i = 0; i < 2; i++){
        int e = tid + i*512; int kq = e >> 3, nq = e & 7;
        cpa(B2 + kq*36 + nq*4, &Bk[(size_t)(256 + kq)*DD + nq*4]);
    }
    COMMIT;
    // G1: B chunk3
    #pragma unroll
    for (int i = 0; i < 2; i++){
        int e = tid + i*512; int kq = e >> 3, nq = e & 7;
        cpa(B3 + kq*36 + nq*4, &Bk[(size_t)(384 + kq)*DD + nq*4]);
    }
    COMMIT;
    int ks = tid >> 6, g = tid & 63, mq4 = (g >> 4) * 4, cv = g & 15;
    u64 a0=0ull, a1=0ull, a2=0ull, a3=0ull;
    WAITG(1);           // Bpre group + G0 done
    __syncthreads();
    chunk16(At + (ks*16)*16 + mq4,        Bpre + (ks*16)*36 + 2*cv, a0,a1,a2,a3);
    chunk16(At + (128 + ks*16)*16 + mq4,  Bpre + 4608 + (ks*16)*36 + 2*cv, a0,a1,a2,a3);
    chunk16(At + (256 + ks*16)*16 + mq4,  B2 + (ks*16)*36 + 2*cv, a0,a1,a2,a3);
    WAITG(0);
    __syncthreads();
    chunk16(At + (384 + ks*16)*16 + mq4,  B3 + (ks*16)*36 + 2*cv, a0,a1,a2,a3);
    sredw(sm, tid, a0,a1,a2,a3);
    return sredr(sm, tid);
}

__global__ __launch_bounds__(512, 1) void k_scan(float* __restrict__ out, int dup) {
    extern __shared__ __align__(16) float sm[];
    __shared__ float red[16];
    int cta = blockIdx.x, tid = threadIdx.x;
    unsigned gen = 0, pgen0 = 0, pgen1 = 0;
    u64* sred = (u64*)(sm + SRED_OFF);
    int m0 = (cta >> 4) * 16, n0 = (cta & 15) * 32;
    int ml = tid >> 4, np = tid & 15;
    int m = m0 + ml, n = n0 + np*2;
    const float* AsrcH0 = (m0 < 64) ? g_Qt : g_Kt;
    int moffH = (m0 < 64) ? m0 : (m0 - 64);

    for (int t = 0; t < TT; t++) {
        // ---- U: gW1 + W1/b1 update (grads of t-1), then prefetch A for H ----
        if (t > 0) {
            float th = g_th[t-1], et = g_et[t-1], al = g_al[t-1];
            float ls = g_loss[t-1] * (1.f/(float)NBD);
            float pt = (ls >= 1e-10f && ls <= 1e10f) ? 1.f : 0.f;
            float s  = th * pt * (2.f/(float)NBD);
            float oa = 1.f - al;
            int i0 = (cta >> 3) * 32, j0 = (cta & 7) * 64;
            float (*sDp)[36] = (float(*)[36])sm;
            float (*sK)[68]  = (float(*)[68])(sm + 2304);
            float (*wT)[36]  = (float(*)[36])(sm + 6656);
            { int b = tid >> 3, iq = tid & 7;
              *(float4*)&sDp[b][iq*4] = *(const float4*)&g_dpre[(size_t)b*DD + i0 + iq*4]; }
            const float* Kt = g_K + (size_t)(t-1)*NBD;
            #pragma unroll
            for (int i = 0; i < 2; i++) {
                int e = tid + i*512; int b = e >> 4, jq = e & 15;
                *(float4*)&sK[b][jq*4] = *(const float4*)&Kt[(size_t)b*DD + j0 + jq*4];
            }
            __syncthreads();
            int ti = tid >> 4, tj = tid & 15;
            u64 a0 = 0ull, a1 = 0ull;
            #pragma unroll 8
            for (int b = 0; b < 64; b++) {
                float av = sDp[b][ti];
                ulonglong2 bv = *(const ulonglong2*)&sK[b][tj*4];
                u64 sx = pk2(av, av);
                fma2(a0, sx, bv.x); fma2(a1, sx, bv.y);
            }
            float2 p0 = up2(a0), p1 = up2(a1);
            int iw = i0 + ti, jw = j0 + tj*4;
            size_t idx = (size_t)iw*DD + jw;
            float4 mm = *(const float4*)&g_M1w[idx];
            float4 ww = *(const float4*)&g_W1[idx];
            mm.x = et*mm.x - s*p0.x; ww.x = oa*ww.x + mm.x;
            mm.y = et*mm.y - s*p0.y; ww.y = oa*ww.y + mm.y;
            mm.z = et*mm.z - s*p1.x; ww.z = oa*ww.z + mm.z;
            mm.w = et*mm.w - s*p1.y; ww.w = oa*ww.w + mm.w;
            *(float4*)&g_M1w[idx] = mm; *(float4*)&g_W1[idx] = ww;
            wT[tj*4+0][ti] = ww.x; wT[tj*4+1][ti] = ww.y;
            wT[tj*4+2][ti] = ww.z; wT[tj*4+3][ti] = ww.w;
            if ((cta & 7) == 0 && tid < 32) {
                int c = i0 + tid; float g = 0.f;
                #pragma unroll 8
                for (int b = 0; b < 64; b++) g += sDp[b][tid];
                float mb = et*g_M1b[c] - s*g; g_M1b[c] = mb; g_b1[c] = oa*g_b1[c] + mb;
            }
            __syncthreads();
            { int jl = tid >> 3, i4 = (tid & 7) * 4;
              *(float4*)&g_W1t[(size_t)(j0+jl)*DD + i0 + i4] = *(float4*)&wT[jl][i4]; }
            preA(sm + AT_OFF, AsrcH0 + (size_t)t*NBD, 64, moffH, tid);
            gbar(gen);
        } else {
            preA(sm + AT_OFF, AsrcH0, 64, moffH, tid);
        }

        // ---- H ----
        {
            float2 rv = sgemmH(g_W1t + n0, sm, tid);
            if (tid < 256) {
                rv.x += g_b1[n]; rv.y += g_b1[n+1];
                *(float2*)&g_h[(size_t)m*DD + n] = rv;
            } else if (tid < 384) {
                int u = tid - 256, nl = u >> 2, m4l = (u & 3) * 4;
                int cv = nl >> 1, half = nl & 1;
                float bb = g_b1[n0 + nl];
                float vals[4];
                #pragma unroll
                for (int j = 0; j < 4; j++) {
                    u64 acc = 0ull;
                    #pragma unroll
                    for (int k2 = 0; k2 < 8; k2++)
                        acc = add2(acc, sred[(k2*16 + m4l + j)*17 + cv]);
                    float2 p = up2(acc);
                    vals[j] = fmaxf((half ? p.y : p.x) + bb, 0.f);
                }
                *(float4*)&g_ht[(size_t)(n0+nl)*128 + m0 + m4l] =
                    make_float4(vals[0], vals[1], vals[2], vals[3]);
            }
            preB2(sm + BP0_OFF, g_W2t + n0, tid);   // prefetch O's B across barrier
        }
        gbar(gen);

        // ---- O ----
        {
            float2 rv = sgemmP(g_ht, 128, m0, g_W2t + n0, sm + BP0_OFF, sm, tid);
            float lsv = 0.f;
            if (tid < 256) {
                rv.x += g_b2[n]; rv.y += g_b2[n+1];
                if (m0 < 64) {
                    size_t o = ((size_t)m*TT + t)*DD + n;
                    *(float2*)&out[o] = rv;
                    if (dup) *(float2*)&out[BTD + o] = rv;
                } else {
                    int b = m - 64;
                    float2 v = *(const float2*)&g_V[(size_t)t*NBD + (size_t)b*DD + n];
                    float d0 = rv.x - v.x, d1 = rv.y - v.y;
                    *(float2*)&g_diff[(size_t)b*DD + n] = make_float2(d0, d1);
                    lsv = d0*d0 + d1*d1;
                }
            } else if (tid < 384 && m0 >= 64) {
                int u = tid - 256, nl = u >> 2, b4l = (u & 3) * 4;
                int cv = nl >> 1, half = nl & 1;
                float bb = g_b2[n0 + nl];
                float vals[4];
                #pragma unroll
                for (int j = 0; j < 4; j++) {
                    u64 acc = 0ull;
                    #pragma unroll
                    for (int k2 = 0; k2 < 8; k2++)
                        acc = add2(acc, sred[(k2*16 + b4l + j)*17 + cv]);
                    float2 p = up2(acc);
                    float val = (half ? p.y : p.x) + bb;
                    vals[j] = val - g_V[(size_t)t*NBD + (size_t)(m0 - 64 + b4l + j)*DD + n0 + nl];
                }
                *(float4*)&g_difft[(size_t)(n0+nl)*64 + (m0 - 64) + b4l] =
                    make_float4(vals[0], vals[1], vals[2], vals[3]);
            }
            if (m0 >= 64) {
                #pragma unroll
                for (int o2 = 16; o2; o2 >>= 1) lsv += __shfl_down_sync(0xffffffffu, lsv, o2);
                if ((tid & 31) == 0) red[tid >> 5] = lsv;
                __syncthreads();
                if (tid == 0) {
                    float sv = 0.f;
                    #pragma unroll
                    for (int i = 0; i < 16; i++) sv += red[i];
                    atomicAdd(&g_loss[t], sv);
                }
            }
            if (t < TT-1 && cta < 64)
                preB2(sm + BP1_OFF, g_W2p[t & 1] + n0, tid);   // prefetch D's B
        }
        if (t == TT-1) break;
        gbar_p(0, pgen0, cta >= 64);

        // ---- D: CTAs 0-63 dpre ; CTAs 64-127 gW2 + fused W2/b2 update ----
        if (cta < 64) {
            float2 rv = sgemmP(g_difft, 64, m0, g_W2p[t & 1] + n0, sm + BP1_OFF, sm, tid);
            if (tid < 256) {
                float2 hp = *(const float2*)&g_h[(size_t)(64 + m)*DD + n];
                *(float2*)&g_dpre[(size_t)m*DD + n] =
                    make_float2(hp.x > 0.f ? rv.x : 0.f, hp.y > 0.f ? rv.y : 0.f);
            }
        } else {
            float th = g_th[t], et = g_et[t], al = g_al[t];
            float ls = g_loss[t] * (1.f/(float)NBD);
            float pt = (ls >= 1e-10f && ls <= 1e10f) ? 1.f : 0.f;
            float s  = th * pt * (2.f/(float)NBD);
            float oa = 1.f - al;
            const float* W2old = g_W2p[t & 1];
            float* W2new = g_W2p[(t + 1) & 1];
            int id = cta - 64;
            int i0 = (id >> 2) * 32, j0 = (id & 3) * 128;
            float (*Ag)[36]  = (float(*)[36])sm;
            float (*Bg)[132] = (float(*)[132])(sm + 2304);
            float (*wT)[36]  = (float(*)[36])(sm + 10752);
            { int b = tid >> 3, iq = tid & 7;
              *(float4*)&Ag[b][iq*4] = *(const float4*)&g_diff[(size_t)b*DD + i0 + iq*4]; }
            #pragma unroll
            for (int i = 0; i < 4; i++) {
                int e = tid + i*512; int b = e >> 5, jq = e & 31;
                float4 v = *(const float4*)&g_h[(size_t)(64 + b)*DD + j0 + jq*4];
                v.x=fmaxf(v.x,0.f); v.y=fmaxf(v.y,0.f); v.z=fmaxf(v.z,0.f); v.w=fmaxf(v.w,0.f);
                *(float4*)&Bg[b][jq*4] = v;
            }
            __syncthreads();
            int ti = tid >> 5, tj = tid & 31;
            u64 q00=0ull, q01=0ull, q10=0ull, q11=0ull;
            #pragma unroll 8
            for (int b = 0; b < 64; b++) {
                float2 av = *(const float2*)&Ag[b][ti*2];
                ulonglong2 bv = *(const ulonglong2*)&Bg[b][tj*4];
                u64 s0 = pk2(av.x,av.x), s1 = pk2(av.y,av.y);
                fma2(q00,s0,bv.x); fma2(q01,s0,bv.y);
                fma2(q10,s1,bv.x); fma2(q11,s1,bv.y);
            }
            float gr[2][4];
            { float2 p;
              p=up2(q00); gr[0][0]=p.x; gr[0][1]=p.y; p=up2(q01); gr[0][2]=p.x; gr[0][3]=p.y;
              p=up2(q10); gr[1][0]=p.x; gr[1][1]=p.y; p=up2(q11); gr[1][2]=p.x; gr[1][3]=p.y; }
            #pragma unroll
            for (int h = 0; h < 2; h++) {
                int iw = i0 + ti*2 + h, jw = j0 + tj*4;
                size_t idx = (size_t)iw*DD + jw;
                float4 mm = *(const float4*)&g_M2w[idx];
                float4 wo = *(const float4*)&W2old[idx];
                mm.x = et*mm.x - s*gr[h][0]; wo.x = oa*wo.x + mm.x;
                mm.y = et*mm.y - s*gr[h][1]; wo.y = oa*wo.y + mm.y;
                mm.z = et*mm.z - s*gr[h][2]; wo.z = oa*wo.z + mm.z;
                mm.w = et*mm.w - s*gr[h][3]; wo.w = oa*wo.w + mm.w;
                *(float4*)&g_M2w[idx] = mm; *(float4*)&W2new[idx] = wo;
                wT[tj*4+0][ti*2+h] = wo.x; wT[tj*4+1][ti*2+h] = wo.y;
                wT[tj*4+2][ti*2+h] = wo.z; wT[tj*4+3][ti*2+h] = wo.w;
            }
            if ((id & 3) == 0 && tid < 32) {
                int c = i0 + tid; float g = 0.f;
                #pragma unroll 8
                for (int b = 0; b < 64; b++) g += Ag[b][tid];
                float m2 = et*g_M2b[c] - s*g; g_M2b[c] = m2; g_b2[c] = oa*g_b2[c] + m2;
            }
            __syncthreads();
            #pragma unroll
            for (int i2 = 0; i2 < 2; i2++) {
                int e = tid + i2*512;
                int jl = e >> 3, i4 = (e & 7) * 4;
                *(float4*)&g_W2t[(size_t)(j0+jl)*DD + i0 + i4] = *(float4*)&wT[jl][i4];
            }
        }
        gbar_p(1, pgen1, cta < 64);
    }
}

extern "C" void kernel_launch(void* const* d_in, const int* in_sizes, int n_in,
                              void* d_out, int out_size) {
    const float* x   = (const float*)d_in[0];
    const float* WQ  = (const float*)d_in[1];
    const float* WK  = (const float*)d_in[2];
    const float* WV  = (const float*)d_in[3];
    const float* thw = (const float*)d_in[4];
    const float* thb = (const float*)d_in[5];
    const float* etw = (const float*)d_in[6];
    const float* etb = (const float*)d_in[7];
    const float* alw = (const float*)d_in[8];
    const float* alb = (const float*)d_in[9];
    const float* W1  = (const float*)d_in[10];
    const float* b1  = (const float*)d_in[11];
    const float* W2  = (const float*)d_in[12];
    const float* b2  = (const float*)d_in[13];
    float* out = (float*)d_out;
    int dup = (out_size >= 2 * BTD) ? 1 : 0;

    cudaFuncSetAttribute(k_scan, cudaFuncAttributeMaxDynamicSharedMemorySize, SCAN_SMEM);
    k_init<<<1024, 256>>>(W1, b1, W2, b2);
    k_gates<<<TT, 256>>>(x, thw, thb, etw, etb, alw, alb);
    k_qkv<<<dim3(8, 128, 3), 256>>>(x, WQ, WK, WV);
    k_scan<<<G_CTAS, 512, SCAN_SMEM>>>(out, dup);
}

// round 17
// speedup vs baseline: 1.0292x; 1.0292x over previous
#include <cuda_runtime.h>
#include <math.h>

#define BB 64
#define TT 128
#define DD 512
#define NBD (BB*DD)
#define BTD (BB*TT*DD)
#define G_CTAS 128
#define SCAN_SMEM 105472   /* 26368 floats */

typedef unsigned long long u64;

__device__ float g_Qt[TT*NBD];     // [t][k][b]
__device__ float g_Kt[TT*NBD];     // [t][k][b]
__device__ float g_K [TT*NBD];     // [t][b][k]
__device__ float g_V [TT*NBD];     // [t][b][k]
__device__ float g_th[TT], g_et[TT], g_al[TT];
__device__ float g_W1[DD*DD], g_M1w[DD*DD], g_b1[DD], g_M1b[DD];
__device__ float g_W2p[2][DD*DD];  // ping-pong row-major W2 (read parity t&1)
__device__ float g_M2w[DD*DD], g_b2[DD], g_M2b[DD];
__device__ float g_W1t[DD*DD], g_W2t[DD*DD];   // [k][n]
__device__ float g_h[2*NBD];       // raw pre-activations
__device__ float g_ht[2*NBD];      // [n][m]  RELU-APPLIED
__device__ float g_diff[NBD];      // [b][n]
__device__ float g_difft[NBD];     // [n][b]
__device__ float g_dpre[NBD];      // [b][n]
__device__ float g_loss[TT];
__device__ unsigned g_barcnt[32][32];
__device__ unsigned g_pcnt[2][8][32];   // partial barriers

__device__ __forceinline__ u64 pk2(float x, float y){
    u64 r; asm("mov.b64 %0, {%1, %2};" : "=l"(r) : "f"(x), "f"(y)); return r;
}
__device__ __forceinline__ void fma2(u64 &c, u64 a, u64 b){
    asm("fma.rn.f32x2 %0, %1, %2, %0;" : "+l"(c) : "l"(a), "l"(b));
}
__device__ __forceinline__ u64 add2(u64 a, u64 b){
    u64 r; asm("add.rn.f32x2 %0, %1, %2;" : "=l"(r) : "l"(a), "l"(b)); return r;
}
__device__ __forceinline__ float2 up2(u64 v){
    float lo, hi; asm("mov.b64 {%0, %1}, %2;" : "=f"(lo), "=f"(hi) : "l"(v));
    return make_float2(lo, hi);
}
__device__ __forceinline__ unsigned smaddr(const void* p){
    return (unsigned)__cvta_generic_to_shared(p);
}

// Full grid barrier: 32 counters (4 CTAs each), warp-parallel acquire poll.
__device__ __forceinline__ void gbar(unsigned &gen){
    __syncthreads();
    if (threadIdx.x < 32){
        if (threadIdx.x == 0){
            unsigned d;
            asm volatile("atom.acq_rel.gpu.global.add.u32 %0, [%1], 1;"
                         : "=r"(d) : "l"(&g_barcnt[blockIdx.x & 31][0]) : "memory");
        }
        unsigned target = (gen + 1u) * 4u, v;
        do {
            asm volatile("ld.acquire.gpu.global.u32 %0, [%1];"
                         : "=r"(v) : "l"(&g_barcnt[threadIdx.x][0]) : "memory");
        } while (__any_sync(0xffffffffu, v < target));
    }
    __syncthreads();
    gen++;
}

// Partial barrier: only 'producer' CTAs arrive (64 of them, 8 per counter); all wait.
__device__ __forceinline__ void gbar_p(int type, unsigned &pgen, bool producer){
    __syncthreads();
    if (threadIdx.x < 8){
        if (threadIdx.x == 0 && producer){
            unsigned d;
            asm volatile("atom.acq_rel.gpu.global.add.u32 %0, [%1], 1;"
                         : "=r"(d) : "l"(&g_pcnt[type][blockIdx.x & 7][0]) : "memory");
        }
        unsigned target = (pgen + 1u) * 8u, v;
        do {
            asm volatile("ld.acquire.gpu.global.u32 %0, [%1];"
                         : "=r"(v) : "l"(&g_pcnt[type][threadIdx.x][0]) : "memory");
        } while (__any_sync(0xffu, v < target));
    }
    __syncthreads();
    pgen++;
}

__global__ void k_init(const float* __restrict__ W1, const float* __restrict__ b1,
                       const float* __restrict__ W2, const float* __restrict__ b2) {
    int i = blockIdx.x * 256 + threadIdx.x;
    if (i < DD*DD) {
        g_W1[i] = W1[i]; g_M1w[i] = 0.f; g_W2p[0][i] = W2[i]; g_M2w[i] = 0.f;
        int tr = (i & 511) * 512 + (i >> 9);
        g_W1t[tr] = W1[i]; g_W2t[tr] = W2[i];
    }
    if (i < DD) { g_b1[i] = b1[i]; g_M1b[i] = 0.f; g_b2[i] = b2[i]; g_M2b[i] = 0.f; }
    if (i < TT) g_loss[i] = 0.f;
    if (i < 1024) ((unsigned*)g_barcnt)[i] = 0u;
    if (i < 512) ((unsigned*)g_pcnt)[i] = 0u;
}

__global__ void k_gates(const float* __restrict__ x,
                        const float* __restrict__ thw, const float* __restrict__ thb,
                        const float* __restrict__ etw, const float* __restrict__ etb,
                        const float* __restrict__ alw, const float* __restrict__ alb) {
    int t = blockIdx.x, tid = threadIdx.x, lane = tid & 31, warp = tid >> 5;
    __shared__ float red[8];
    for (int g = 0; g < 3; g++) {
        const float* w = (g == 0) ? thw : ((g == 1) ? etw : alw);
        float b0 = (g == 0) ? thb[0] : ((g == 1) ? etb[0] : alb[0]);
        float acc = 0.f;
        for (int bi = warp; bi < BB; bi += 8) {
            const float* xr = x + ((size_t)bi * TT + t) * DD;
            float s = 0.f;
            for (int k = lane; k < DD; k += 32) s += xr[k] * w[k];
            #pragma unroll
            for (int o = 16; o; o >>= 1) s += __shfl_down_sync(0xffffffffu, s, o);
            if (lane == 0) acc += 1.f / (1.f + expf(-(s + b0)));
        }
        if (lane == 0) red[warp] = acc;
        __syncthreads();
        if (tid == 0) {
            float s = 0.f;
            #pragma unroll
            for (int i = 0; i < 8; i++) s += red[i];
            s *= (1.f / (float)BB);
            if (g == 0) g_th[t] = s; else if (g == 1) g_et[t] = s; else g_al[t] = s;
        }
        __syncthreads();
    }
}

// QKV: 64x64 tiles, register double-buffered smem stages, 1 sync per 32-k chunk.
__global__ __launch_bounds__(256) void k_qkv(const float* __restrict__ x,
                       const float* __restrict__ WQ, const float* __restrict__ WK,
                       const float* __restrict__ WV) {
    __shared__ __align__(16) float qsm[8704];   // 2 stages x (A 32x68 + B 32x68)
    int n0 = blockIdx.x * 64, m0 = blockIdx.y * 64, z = blockIdx.z;
    const float* W = (z == 0) ? WQ : ((z == 1) ? WK : WV);
    int tid = threadIdx.x;
    int r0 = (tid >> 4) * 4, c0 = (tid & 15) * 4;
    int row0 = tid >> 3, kq0 = tid & 7;             // element 0
    int row1 = (tid + 256) >> 3, kq1 = tid & 7;     // element 1
    int mm0 = m0 + row0, mm1 = m0 + row1;
    const float* xr0 = &x[((size_t)(mm0 & 63)*TT + (mm0 >> 6))*DD + kq0*4];
    const float* xr1 = &x[((size_t)(mm1 & 63)*TT + (mm1 >> 6))*DD + kq1*4];
    const float* wr0 = &W[(size_t)(n0 + row0)*DD + kq0*4];
    const float* wr1 = &W[(size_t)(n0 + row1)*DD + kq1*4];
    u64 acc[4][2];
    #pragma unroll
    for (int i = 0; i < 4; i++) { acc[i][0] = 0ull; acc[i][1] = 0ull; }
    float4 xa0, xa1, wa0, wa1;
    // prologue: load + store chunk 0
    xa0 = *(const float4*)(xr0);      xa1 = *(const float4*)(xr1);
    wa0 = *(const float4*)(wr0);      wa1 = *(const float4*)(wr1);
    {
        float* A = qsm; float* B = qsm + 2176;
        A[(4*kq0+0)*68+row0]=xa0.x; A[(4*kq0+1)*68+row0]=xa0.y; A[(4*kq0+2)*68+row0]=xa0.z; A[(4*kq0+3)*68+row0]=xa0.w;
        A[(4*kq1+0)*68+row1]=xa1.x; A[(4*kq1+1)*68+row1]=xa1.y; A[(4*kq1+2)*68+row1]=xa1.z; A[(4*kq1+3)*68+row1]=xa1.w;
        B[(4*kq0+0)*68+row0]=wa0.x; B[(4*kq0+1)*68+row0]=wa0.y; B[(4*kq0+2)*68+row0]=wa0.z; B[(4*kq0+3)*68+row0]=wa0.w;
        B[(4*kq1+0)*68+row1]=wa1.x; B[(4*kq1+1)*68+row1]=wa1.y; B[(4*kq1+2)*68+row1]=wa1.z; B[(4*kq1+3)*68+row1]=wa1.w;
    }
    __syncthreads();
    for (int kb = 0; kb < 16; kb++) {
        if (kb < 15) {
            int o = (kb+1)*32;
            xa0 = *(const float4*)(xr0 + o);  xa1 = *(const float4*)(xr1 + o);
            wa0 = *(const float4*)(wr0 + o);  wa1 = *(const float4*)(wr1 + o);
        }
        const float* Ab = qsm + (kb & 1)*4352;
        const float* Bb = Ab + 2176;
        #pragma unroll 8
        for (int kk = 0; kk < 32; kk++) {
            float4 a4 = *(const float4*)&Ab[kk*68 + r0];
            ulonglong2 bb = *(const ulonglong2*)&Bb[kk*68 + c0];
            u64 sx;
            sx = pk2(a4.x,a4.x); fma2(acc[0][0],sx,bb.x); fma2(acc[0][1],sx,bb.y);
            sx = pk2(a4.y,a4.y); fma2(acc[1][0],sx,bb.x); fma2(acc[1][1],sx,bb.y);
            sx = pk2(a4.z,a4.z); fma2(acc[2][0],sx,bb.x); fma2(acc[2][1],sx,bb.y);
            sx = pk2(a4.w,a4.w); fma2(acc[3][0],sx,bb.x); fma2(acc[3][1],sx,bb.y);
        }
        if (kb < 15) {
            float* A = qsm + ((kb+1) & 1)*4352;
            float* B = A + 2176;
            A[(4*kq0+0)*68+row0]=xa0.x; A[(4*kq0+1)*68+row0]=xa0.y; A[(4*kq0+2)*68+row0]=xa0.z; A[(4*kq0+3)*68+row0]=xa0.w;
            A[(4*kq1+0)*68+row1]=xa1.x; A[(4*kq1+1)*68+row1]=xa1.y; A[(4*kq1+2)*68+row1]=xa1.z; A[(4*kq1+3)*68+row1]=xa1.w;
            B[(4*kq0+0)*68+row0]=wa0.x; B[(4*kq0+1)*68+row0]=wa0.y; B[(4*kq0+2)*68+row0]=wa0.z; B[(4*kq0+3)*68+row0]=wa0.w;
            B[(4*kq1+0)*68+row1]=wa1.x; B[(4*kq1+1)*68+row1]=wa1.y; B[(4*kq1+2)*68+row1]=wa1.z; B[(4*kq1+3)*68+row1]=wa1.w;
        }
        __syncthreads();
    }
    float (*T)[68] = (float(*)[68])qsm;
    #pragma unroll
    for (int i = 0; i < 4; i++) {
        float2 p0 = up2(acc[i][0]), p1 = up2(acc[i][1]);
        float4 v = make_float4(p0.x, p0.y, p1.x, p1.y);
        if (z == 2) { *(float4*)&g_V[(size_t)(m0+r0+i)*DD + n0 + c0] = v; }
        else {
            if (z == 1) *(float4*)&g_K[(size_t)(m0+r0+i)*DD + n0 + c0] = v;
            T[c0+0][r0+i] = p0.x; T[c0+1][r0+i] = p0.y;
            T[c0+2][r0+i] = p1.x; T[c0+3][r0+i] = p1.y;
        }
    }
    if (z < 2) {
        __syncthreads();
        float* Ot = ((z == 0) ? g_Qt : g_Kt) + (size_t)(m0 >> 6)*NBD;
        #pragma unroll
        for (int i = 0; i < 4; i++) {
            int e = tid + i*256;
            int nl = e >> 4, b4 = (e & 15) * 4;
            *(float4*)&Ot[(size_t)(n0 + nl)*64 + b4] = *(float4*)&T[nl][b4];
        }
    }
}

// C[16x32] = A(k-major [512][Ms], rows moff..+16) @ Bk(k-major rows, stride DD, 32 cols)
// 512 threads, split-K x8, 3-buffer cp.async(.cg) pipeline, 1 sync/chunk.
// Result for tid<256 at (m = tid>>4, n-pair = tid&15). Partials stay in sred.
__device__ __forceinline__ float2 sgemm6(const float* __restrict__ Akt, int Ms, int moff,
                                         const float* __restrict__ Bk,
                                         float* sm, int tid) {
    float* At  = sm;                       // 512*16
    float* Bs  = sm + 8192;                // 3 x 128*36
    u64*  sred = (u64*)(sm + 22016);       // 8*16*17
    #pragma unroll
    for (int i = 0; i < 4; i++) {
        int e = tid + i*512; int k = e >> 2, mq4 = (e & 3) * 4;
        unsigned dst = smaddr(&At[k*16 + mq4]);
        const float* src = &Akt[(size_t)k*Ms + moff + mq4];
        asm volatile("cp.async.cg.shared.global [%0], [%1], 16;" :: "r"(dst), "l"(src));
    }
    #pragma unroll
    for (int i = 0; i < 2; i++) {
        int e = tid + i*512; int kq = e >> 3, nq = e & 7;
        unsigned dst = smaddr(&Bs[kq*36 + nq*4]);
        const float* src = &Bk[(size_t)kq*DD + nq*4];
        asm volatile("cp.async.cg.shared.global [%0], [%1], 16;" :: "r"(dst), "l"(src));
    }
    asm volatile("cp.async.commit_group;");
    #pragma unroll
    for (int c = 1; c < 3; c++) {
        #pragma unroll
        for (int i = 0; i < 2; i++) {
            int e = tid + i*512; int kq = e >> 3, nq = e & 7;
            unsigned dst = smaddr(&Bs[c*4608 + kq*36 + nq*4]);
            const float* src = &Bk[(size_t)(c*128 + kq)*DD + nq*4];
            asm volatile("cp.async.cg.shared.global [%0], [%1], 16;" :: "r"(dst), "l"(src));
        }
        asm volatile("cp.async.commit_group;");
    }
    int ks = tid >> 6, g = tid & 63, mq4 = (g >> 4) * 4, cv = g & 15;
    u64 ac0=0ull, ac1=0ull, ac2=0ull, ac3=0ull;
    #pragma unroll
    for (int c = 0; c < 4; c++) {
        if (c == 0) asm volatile("cp.async.wait_group 2;");
        else if (c == 3) asm volatile("cp.async.wait_group 0;");
        else asm volatile("cp.async.wait_group 1;");
        __syncthreads();
        if (c == 1) {
            #pragma unroll
            for (int i = 0; i < 2; i++) {
                int e = tid + i*512; int kq = e >> 3, nq = e & 7;
                unsigned dst = smaddr(&Bs[kq*36 + nq*4]);
                const float* src = &Bk[(size_t)(384 + kq)*DD + nq*4];
                asm volatile("cp.async.cg.shared.global [%0], [%1], 16;" :: "r"(dst), "l"(src));
            }
            asm volatile("cp.async.commit_group;");
        }
        const float* ap = At + (c*128 + ks*16)*16 + mq4;
        const float* bp = Bs + (c%3)*4608 + (ks*16)*36 + 2*cv;
        #pragma unroll
        for (int kk = 0; kk < 16; kk++) {
            float4 a = *(const float4*)(ap + kk*16);
            u64 b = *(const u64*)(bp + kk*36);
            fma2(ac0, pk2(a.x,a.x), b);
            fma2(ac1, pk2(a.y,a.y), b);
            fma2(ac2, pk2(a.z,a.z), b);
            fma2(ac3, pk2(a.w,a.w), b);
        }
    }
    u64* rp = &sred[(ks*16 + mq4)*17 + cv];
    rp[0] = ac0; rp[17] = ac1; rp[34] = ac2; rp[51] = ac3;
    __syncthreads();
    float2 T = make_float2(0.f, 0.f);
    if (tid < 256) {
        int m = tid >> 4, cvv = tid & 15;
        u64 acc = 0ull;
        #pragma unroll
        for (int k2 = 0; k2 < 8; k2++)
            acc = add2(acc, sred[(k2*16 + m)*17 + cvv]);
        T = up2(acc);
    }
    return T;
}

__global__ __launch_bounds__(512, 1) void k_scan(float* __restrict__ out, int dup) {
    extern __shared__ __align__(16) float sm[];
    __shared__ float red[16];
    int cta = blockIdx.x, tid = threadIdx.x;
    unsigned gen = 0, pgen0 = 0, pgen1 = 0;
    u64* sred = (u64*)(sm + 22016);

    for (int t = 0; t < TT; t++) {
        // ---- U: gW1 + W1/b1 update (grads of t-1) ----
        if (t > 0) {
            float th = g_th[t-1], et = g_et[t-1], al = g_al[t-1];
            float ls = g_loss[t-1] * (1.f/(float)NBD);
            float pt = (ls >= 1e-10f && ls <= 1e10f) ? 1.f : 0.f;
            float s  = th * pt * (2.f/(float)NBD);
            float oa = 1.f - al;
            int i0 = (cta >> 3) * 32, j0 = (cta & 7) * 64;
            float (*sDp)[36] = (float(*)[36])sm;               // 64x36
            float (*sK)[68]  = (float(*)[68])(sm + 2304);      // 64x68
            float (*wT)[36]  = (float(*)[36])(sm + 6656);      // 64x36
            { int b = tid >> 3, iq = tid & 7;
              *(float4*)&sDp[b][iq*4] = *(const float4*)&g_dpre[(size_t)b*DD + i0 + iq*4]; }
            const float* Kt = g_K + (size_t)(t-1)*NBD;
            #pragma unroll
            for (int i = 0; i < 2; i++) {
                int e = tid + i*512; int b = e >> 4, jq = e & 15;
                *(float4*)&sK[b][jq*4] = *(const float4*)&Kt[(size_t)b*DD + j0 + jq*4];
            }
            __syncthreads();
            int ti = tid >> 4, tj = tid & 15;
            u64 a0 = 0ull, a1 = 0ull;
            #pragma unroll 8
            for (int b = 0; b < 64; b++) {
                float av = sDp[b][ti];
                ulonglong2 bv = *(const ulonglong2*)&sK[b][tj*4];
                u64 sx = pk2(av, av);
                fma2(a0, sx, bv.x); fma2(a1, sx, bv.y);
            }
            float2 p0 = up2(a0), p1 = up2(a1);
            int iw = i0 + ti, jw = j0 + tj*4;
            size_t idx = (size_t)iw*DD + jw;
            float4 mm = *(const float4*)&g_M1w[idx];
            float4 ww = *(const float4*)&g_W1[idx];
            mm.x = et*mm.x - s*p0.x; ww.x = oa*ww.x + mm.x;
            mm.y = et*mm.y - s*p0.y; ww.y = oa*ww.y + mm.y;
            mm.z = et*mm.z - s*p1.x; ww.z = oa*ww.z + mm.z;
            mm.w = et*mm.w - s*p1.y; ww.w = oa*ww.w + mm.w;
            *(float4*)&g_M1w[idx] = mm; *(float4*)&g_W1[idx] = ww;
            wT[tj*4+0][ti] = ww.x; wT[tj*4+1][ti] = ww.y;
            wT[tj*4+2][ti] = ww.z; wT[tj*4+3][ti] = ww.w;
            if ((cta & 7) == 0 && tid < 32) {
                int c = i0 + tid; float g = 0.f;
                #pragma unroll 8
                for (int b = 0; b < 64; b++) g += sDp[b][tid];
                float m = et*g_M1b[c] - s*g; g_M1b[c] = m; g_b1[c] = oa*g_b1[c] + m;
            }
            __syncthreads();
            { int jl = tid >> 3, i4 = (tid & 7) * 4;
              *(float4*)&g_W1t[(size_t)(j0+jl)*DD + i0 + i4] = *(float4*)&wT[jl][i4]; }
            gbar(gen);
        }

        int m0 = (cta >> 4) * 16, n0 = (cta & 15) * 32;
        int ml = tid >> 4, np = tid & 15;
        int m = m0 + ml, n = n0 + np*2;

        // ---- H:  h = [q;k]@W1^T + b1 ; ht (relu) written by transposed reducers ----
        {
            const float* Akt = (m0 < 64) ? (g_Qt + (size_t)t*NBD) : (g_Kt + (size_t)t*NBD);
            int moff = (m0 < 64) ? m0 : (m0 - 64);
            float2 rv = sgemm6(Akt, 64, moff, g_W1t + n0, sm, tid);
            if (tid < 256) {
                rv.x += g_b1[n]; rv.y += g_b1[n+1];
                *(float2*)&g_h[(size_t)m*DD + n] = rv;
            } else if (tid < 384) {
                int u = tid - 256, nl = u >> 2, m4l = (u & 3) * 4;
                int cv = nl >> 1, half = nl & 1;
                float bb = g_b1[n0 + nl];
                float vals[4];
                #pragma unroll
                for (int j = 0; j < 4; j++) {
                    u64 acc = 0ull;
                    #pragma unroll
                    for (int k2 = 0; k2 < 8; k2++)
                        acc = add2(acc, sred[(k2*16 + m4l + j)*17 + cv]);
                    float2 p = up2(acc);
                    vals[j] = fmaxf((half ? p.y : p.x) + bb, 0.f);
                }
                *(float4*)&g_ht[(size_t)(n0+nl)*128 + m0 + m4l] =
                    make_float4(vals[0], vals[1], vals[2], vals[3]);
            }
        }
        gbar(gen);

        // ---- O ----
        {
            float2 rv = sgemm6(g_ht, 128, m0, g_W2t + n0, sm, tid);
            float lsv = 0.f;
            if (tid < 256) {
                rv.x += g_b2[n]; rv.y += g_b2[n+1];
                if (m0 < 64) {
                    size_t o = ((size_t)m*TT + t)*DD + n;
                    *(float2*)&out[o] = rv;
                    if (dup) *(float2*)&out[BTD + o] = rv;
                } else {
                    int b = m - 64;
                    float2 v = *(const float2*)&g_V[(size_t)t*NBD + (size_t)b*DD + n];
                    float d0 = rv.x - v.x, d1 = rv.y - v.y;
                    *(float2*)&g_diff[(size_t)b*DD + n] = make_float2(d0, d1);
                    lsv = d0*d0 + d1*d1;
                }
            } else if (tid < 384 && m0 >= 64) {
                int u = tid - 256, nl = u >> 2, b4l = (u & 3) * 4;
                int cv = nl >> 1, half = nl & 1;
                float bb = g_b2[n0 + nl];
                float vals[4];
                #pragma unroll
                for (int j = 0; j < 4; j++) {
                    u64 acc = 0ull;
                    #pragma unroll
                    for (int k2 = 0; k2 < 8; k2++)
                        acc = add2(acc, sred[(k2*16 + b4l + j)*17 + cv]);
                    float2 p = up2(acc);
                    float val = (half ? p.y : p.x) + bb;
                    vals[j] = val - g_V[(size_t)t*NBD + (size_t)(m0 - 64 + b4l + j)*DD + n0 + nl];
                }
                *(float4*)&g_difft[(size_t)(n0+nl)*64 + (m0 - 64) + b4l] =
                    make_float4(vals[0], vals[1], vals[2], vals[3]);
            }
            if (m0 >= 64) {
                #pragma unroll
                for (int o2 = 16; o2; o2 >>= 1) lsv += __shfl_down_sync(0xffffffffu, lsv, o2);
                if ((tid & 31) == 0) red[tid >> 5] = lsv;
                __syncthreads();
                if (tid == 0) {
                    float sv = 0.f;
                    #pragma unroll
                    for (int i = 0; i < 16; i++) sv += red[i];
                    atomicAdd(&g_loss[t], sv);
                }
            }
        }
        if (t == TT-1) break;
        gbar_p(0, pgen0, cta >= 64);   // only k-path producers gate D

        // ---- D: CTAs 0-63 dpre ; CTAs 64-127 gW2 + fused W2/b2 update ----
        if (cta < 64) {
            int m0d = (cta >> 4) * 16, n0d = (cta & 15) * 32;
            float2 rv = sgemm6(g_difft, 64, m0d, g_W2p[t & 1] + n0d, sm, tid);
            if (tid < 256) {
                int md = m0d + ml, nd = n0d + np*2;
                float2 hp = *(const float2*)&g_h[(size_t)(64 + md)*DD + nd];
                *(float2*)&g_dpre[(size_t)md*DD + nd] =
                    make_float2(hp.x > 0.f ? rv.x : 0.f, hp.y > 0.f ? rv.y : 0.f);
            }
        } else {
            float th = g_th[t], et = g_et[t], al = g_al[t];
            float ls = g_loss[t] * (1.f/(float)NBD);
            float pt = (ls >= 1e-10f && ls <= 1e10f) ? 1.f : 0.f;
            float s  = th * pt * (2.f/(float)NBD);
            float oa = 1.f - al;
            const float* W2old = g_W2p[t & 1];
            float* W2new = g_W2p[(t + 1) & 1];
            int id = cta - 64;
            int i0 = (id >> 2) * 32, j0 = (id & 3) * 128;
            float (*Ag)[36]  = (float(*)[36])sm;               // 64x36
            float (*Bg)[132] = (float(*)[132])(sm + 2304);     // 64x132
            float (*wT)[36]  = (float(*)[36])(sm + 10752);     // 128x36
            { int b = tid >> 3, iq = tid & 7;
              *(float4*)&Ag[b][iq*4] = *(const float4*)&g_diff[(size_t)b*DD + i0 + iq*4]; }
            #pragma unroll
            for (int i = 0; i < 4; i++) {
                int e = tid + i*512; int b = e >> 5, jq = e & 31;
                float4 v = *(const float4*)&g_h[(size_t)(64 + b)*DD + j0 + jq*4];
                v.x=fmaxf(v.x,0.f); v.y=fmaxf(v.y,0.f); v.z=fmaxf(v.z,0.f); v.w=fmaxf(v.w,0.f);
                *(float4*)&Bg[b][jq*4] = v;
            }
            __syncthreads();
            int ti = tid >> 5, tj = tid & 31;
            u64 q00=0ull, q01=0ull, q10=0ull, q11=0ull;
            #pragma unroll 8
            for (int b = 0; b < 64; b++) {
                float2 av = *(const float2*)&Ag[b][ti*2];
                ulonglong2 bv = *(const ulonglong2*)&Bg[b][tj*4];
                u64 s0 = pk2(av.x,av.x), s1 = pk2(av.y,av.y);
                fma2(q00,s0,bv.x); fma2(q01,s0,bv.y);
                fma2(q10,s1,bv.x); fma2(q11,s1,bv.y);
            }
            float gr[2][4];
            { float2 p;
              p=up2(q00); gr[0][0]=p.x; gr[0][1]=p.y; p=up2(q01); gr[0][2]=p.x; gr[0][3]=p.y;
              p=up2(q10); gr[1][0]=p.x; gr[1][1]=p.y; p=up2(q11); gr[1][2]=p.x; gr[1][3]=p.y; }
            #pragma unroll
            for (int h = 0; h < 2; h++) {
                int iw = i0 + ti*2 + h, jw = j0 + tj*4;
                size_t idx = (size_t)iw*DD + jw;
                float4 mm = *(const float4*)&g_M2w[idx];
                float4 wo = *(const float4*)&W2old[idx];
                mm.x = et*mm.x - s*gr[h][0]; wo.x = oa*wo.x + mm.x;
                mm.y = et*mm.y - s*gr[h][1]; wo.y = oa*wo.y + mm.y;
                mm.z = et*mm.z - s*gr[h][2]; wo.z = oa*wo.z + mm.z;
                mm.w = et*mm.w - s*gr[h][3]; wo.w = oa*wo.w + mm.w;
                *(float4*)&g_M2w[idx] = mm; *(float4*)&W2new[idx] = wo;
                wT[tj*4+0][ti*2+h] = wo.x; wT[tj*4+1][ti*2+h] = wo.y;
                wT[tj*4+2][ti*2+h] = wo.z; wT[tj*4+3][ti*2+h] = wo.w;
            }
            if ((id & 3) == 0 && tid < 32) {
                int c = i0 + tid; float g = 0.f;
                #pragma unroll 8
                for (int b = 0; b < 64; b++) g += Ag[b][tid];
                float m2 = et*g_M2b[c] - s*g; g_M2b[c] = m2; g_b2[c] = oa*g_b2[c] + m2;
            }
            __syncthreads();
            #pragma unroll
            for (int i2 = 0; i2 < 2; i2++) {
                int e = tid + i2*512;
                int jl = e >> 3, i4 = (e & 7) * 4;
                *(float4*)&g_W2t[(size_t)(j0+jl)*DD + i0 + i4] = *(float4*)&wT[jl][i4];
            }
        }
        gbar_p(1, pgen1, cta < 64);    // only dpre producers gate U
    }
}

extern "C" void kernel_launch(void* const* d_in, const int* in_sizes, int n_in,
                              void* d_out, int out_size) {
    const float* x   = (const float*)d_in[0];
    const float* WQ  = (const float*)d_in[1];
    const float* WK  = (const float*)d_in[2];
    const float* WV  = (const float*)d_in[3];
    const float* thw = (const float*)d_in[4];
    const float* thb = (const float*)d_in[5];
    const float* etw = (const float*)d_in[6];
    const float* etb = (const float*)d_in[7];
    const float* alw = (const float*)d_in[8];
    const float* alb = (const float*)d_in[9];
    const float* W1  = (const float*)d_in[10];
    const float* b1  = (const float*)d_in[11];
    const float* W2  = (const float*)d_in[12];
    const float* b2  = (const float*)d_in[13];
    float* out = (float*)d_out;
    int dup = (out_size >= 2 * BTD) ? 1 : 0;

    cudaFuncSetAttribute(k_scan, cudaFuncAttributeMaxDynamicSharedMemorySize, SCAN_SMEM);
    k_init<<<1024, 256>>>(W1, b1, W2, b2);
    k_gates<<<TT, 256>>>(x, thw, thb, etw, etb, alw, alb);
    k_qkv<<<dim3(8, 128, 3), 256>>>(x, WQ, WK, WV);
    k_scan<<<G_CTAS, 512, SCAN_SMEM>>>(out, dup);
}